// round 11
// baseline (speedup 1.0000x reference)
#include <cuda_runtime.h>
#include <math.h>

// Fixed dataset shape: B=64, NCROPS=2, T=2048, nb=32
#define TT   2048
#define NW64 64         // mask words (TT/32)
#define NT   512        // 16 warps: group0 = warps 0-7 (fwd), group1 = warps 8-15 (bwd)
#define GT   256        // threads per group
#define GCH  8          // elements per thread in group phases
#define CH4  4          // elements per thread in full-block phases
#define ALPHA_F 0.7f
#define MIN_MINING_STEP 50
#define BIGF 3.0e38f

__device__ float g_partial[64];
__device__ int   g_count = 0;

// group barrier (named): only the 256 threads of one group participate
__device__ __forceinline__ void gbar(int id) {
    asm volatile("bar.sync %0, %1;" :: "r"(id), "r"(GT) : "memory");
}

// ---- mining monoid: function (okIn,anchIn,hasIn) -> (okOut,anchOut,hasOut) ----
// fl bit0 = hasAnchor, bit1 = okPost (ok after last internal anchor)
struct MF { int fl; float aOut; float mPre; };

__device__ __forceinline__ MF mcomp(const MF L, const MF R) {
    MF C;
    const int lh = L.fl & 1, rh = R.fl & 1;
    C.aOut = rh ? R.aOut : L.aOut;
    C.mPre = lh ? L.mPre : fminf(L.mPre, R.mPre);
    int kp = rh ? (R.fl >> 1)
                : ((L.fl >> 1) & ((R.mPre >= ALPHA_F * L.aOut) ? 1 : 0));
    C.fl = (lh | rh) | ((kp & 1) << 1);
    return C;
}

// One mining direction. Returns the thread's 8-bit grown mask (bit k = idx base+k
// in direction coordinates). Exact replay of the jax scan recurrence.
__device__ __forceinline__ unsigned mine_dir(
    const float* sv, unsigned amask,
    int* sfl, float* sa, float* sm,
    int lane, int wig, int wg, int barId, int rev, int L, int base)
{
    // pass 1: serial thread aggregate (compose 8 element functions)
    MF acc;
    #pragma unroll
    for (int k = 0; k < GCH; ++k) {
        float s = sv[k];
        int   a = (amask >> k) & 1;
        MF e; e.fl = a ? 3 : 2; e.aOut = a ? s : 0.0f; e.mPre = a ? BIGF : s;
        acc = (k == 0) ? e : mcomp(acc, e);
    }

    // warp inclusive scan
    MF inc = acc;
    #pragma unroll
    for (int d = 1; d < 32; d <<= 1) {
        MF v;
        v.fl   = __shfl_up_sync(0xffffffffu, inc.fl,   d);
        v.aOut = __shfl_up_sync(0xffffffffu, inc.aOut, d);
        v.mPre = __shfl_up_sync(0xffffffffu, inc.mPre, d);
        if (lane >= d) inc = mcomp(v, inc);
    }
    if (lane == 31) { sfl[wg] = inc.fl; sa[wg] = inc.aOut; sm[wg] = inc.mPre; }
    gbar(barId);

    // cross-warp prefix: 8-lane mini scan over this group's warp aggregates
    const int wbase = wg - wig;
    MF wv;
    {
        int idxw = wbase + (lane & 7);
        wv.fl = sfl[idxw]; wv.aOut = sa[idxw]; wv.mPre = sm[idxw];
    }
    #pragma unroll
    for (int d = 1; d < 8; d <<= 1) {
        MF u;
        u.fl   = __shfl_up_sync(0xffffffffu, wv.fl,   d);
        u.aOut = __shfl_up_sync(0xffffffffu, wv.aOut, d);
        u.mPre = __shfl_up_sync(0xffffffffu, wv.mPre, d);
        if (lane >= d) wv = mcomp(u, wv);
    }
    MF wp;
    wp.fl   = __shfl_sync(0xffffffffu, wv.fl,   wig - 1);
    wp.aOut = __shfl_sync(0xffffffffu, wv.aOut, wig - 1);
    wp.mPre = __shfl_sync(0xffffffffu, wv.mPre, wig - 1);
    const int hasWp = (wig > 0);

    // thread-exclusive within warp
    MF te;
    te.fl   = __shfl_up_sync(0xffffffffu, inc.fl,   1);
    te.aOut = __shfl_up_sync(0xffffffffu, inc.aOut, 1);
    te.mPre = __shfl_up_sync(0xffffffffu, inc.mPre, 1);
    const int hasTe = (lane > 0);
    MF P; int hasP = 0;
    if (hasWp && hasTe)      { P = mcomp(wp, te); hasP = 1; }
    else if (hasWp)          { P = wp;            hasP = 1; }
    else if (hasTe)          { P = te;            hasP = 1; }

    // apply prefix to canonical init (ok=true, anch=0, has=false)
    int   has  = hasP ? (P.fl & 1) : 0;
    int   ok   = has ? ((P.fl >> 1) & 1) : 1;
    float anch = has ? P.aOut : 0.0f;

    // pass 2: serial replay emitting grown bits
    unsigned gmask = 0;
    #pragma unroll
    for (int k = 0; k < GCH; ++k) {
        float s = sv[k];
        int   a = (amask >> k) & 1;
        int cond  = (s >= ALPHA_F * anch) ? 1 : 0;
        int grown = ok & cond & has;
        if (!rev) {                       // fwd masked by seqlen
            int pos = base + k;
            grown &= (pos < L) ? 1 : 0;
        }
        gmask |= ((unsigned)grown) << k;
        ok   = a ? 1 : grown;
        anch = a ? s : anch;
        has |= a;
    }
    return gmask;
}

__global__ __launch_bounds__(NT, 1)
void glance_fused(const float* __restrict__ scores,
                  const int* __restrict__ point_label,
                  const int* __restrict__ seqlen,
                  const int* __restrict__ step_p,
                  float* __restrict__ out)
{
    const int b = blockIdx.x;
    const int t = threadIdx.x;

    __shared__ float sprob[TT];
    __shared__ unsigned maskA[NW64];   // anchors (phase 1)
    __shared__ int      maskG[NW64];   // mined growth (phase 2), OR'd atomically
    __shared__ int   sfl[16]; __shared__ float sa[16]; __shared__ float sm[16];
    __shared__ int   rdm[16];
    __shared__ float rsv[16], rsgd[16], rsd[16];

    // early scalar loads (overlap with phase 1 DRAM latency)
    const int L   = seqlen[b];
    const int stp = step_p[0];

    const int lane = t & 31, wg = t >> 5, grp = t >> 8, wig = wg & 7;
    const int gt = t & (GT - 1), barId = 1 + grp;
    const int base4 = t * CH4;

    // Phase 1: vectorized sigmoid + crop-mean. Only p and 1-p computed here
    // (3 MUFU/elem); BCE logs deferred to phase 4.
    const float4* r0 = (const float4*)(scores + (size_t)(2 * b) * TT);
    const float4* r1 = (const float4*)(scores + (size_t)(2 * b + 1) * TT);
    const int4*   pl = (const int4*)(point_label + (size_t)b * TT);
    const float4 avv = r0[t];
    const float4 cvv = r1[t];
    const int4   qvv = pl[t];
    const float aa[4] = {avv.x, avv.y, avv.z, avv.w};
    const float cc[4] = {cvv.x, cvv.y, cvv.z, cvv.w};
    const int   qq4[4] = {qvv.x, qvv.y, qvv.z, qvv.w};
    float pp[CH4], qq[CH4];
    unsigned nib = 0;
    #pragma unroll
    for (int k = 0; k < CH4; ++k) {
        float ea = __expf(-aa[k]);
        float ec = __expf(-cc[k]);
        float n1 = 2.0f + ea + ec;
        float n2 = fmaf(2.0f * ea, ec, ea + ec);
        float rc = __frcp_rn(n1 + n2);
        float p  = n1 * rc;
        sprob[base4 + k] = p;
        pp[k] = p;
        qq[k] = n2 * rc;
        nib |= ((qq4[k] > 0) ? 1u : 0u) << k;
    }
    // anchor bitmask: 8 consecutive threads' nibbles -> one 32-bit word
    {
        unsigned v = nib << ((t & 7) * 4);
        v |= __shfl_xor_sync(0xffffffffu, v, 1);
        v |= __shfl_xor_sync(0xffffffffu, v, 2);
        v |= __shfl_xor_sync(0xffffffffu, v, 4);
        if ((t & 7) == 0) maskA[t >> 3] = v;
    }
    if (t < NW64) maskG[t] = 0;
    __syncthreads();

    // Phase 2: mining — fwd (group 0) and bwd (group 1) run CONCURRENTLY.
    if (stp >= MIN_MINING_STEP) {
        const int gbase = gt * GCH;
        const float4* sp4 = (const float4*)sprob;
        float sv[GCH]; unsigned amask; int widx; unsigned plshift; int rb = 0;
        if (grp == 0) {
            float4 f0 = sp4[gbase >> 2], f1 = sp4[(gbase >> 2) + 1];
            sv[0]=f0.x; sv[1]=f0.y; sv[2]=f0.z; sv[3]=f0.w;
            sv[4]=f1.x; sv[5]=f1.y; sv[6]=f1.z; sv[7]=f1.w;
            amask = (maskA[gt >> 2] >> ((gt & 3) * 8)) & 0xffu;
            widx = gt >> 2; plshift = (gt & 3) * 8;
        } else {
            const int q = TT - 8 - gbase;      // lowest position of this byte
            float4 f0 = sp4[q >> 2], f1 = sp4[(q >> 2) + 1];
            sv[0]=f1.w; sv[1]=f1.z; sv[2]=f1.y; sv[3]=f1.x;
            sv[4]=f0.w; sv[5]=f0.z; sv[6]=f0.y; sv[7]=f0.x;
            unsigned byte = (maskA[q >> 5] >> (q & 24)) & 0xffu;
            amask = __brev(byte) >> 24;
            widx = q >> 5; plshift = q & 24; rb = 1;
        }
        unsigned gmask = mine_dir(sv, amask, sfl, sa, sm,
                                  lane, wig, wg, barId, grp, L, gbase);
        unsigned bytev = rb ? (__brev(gmask) >> 24) : gmask;
        unsigned v = bytev << plshift;
        v |= __shfl_xor_sync(0xffffffffu, v, 1);
        v |= __shfl_xor_sync(0xffffffffu, v, 2);
        if ((gt & 3) == 0 && v) atomicOr(&maskG[widx], (int)v);
    }
    __syncthreads();

    // Phase 3+4 fused: O(1) nearest-set distance from bitmask + splat + BCE.
    const int w = t >> 3;
    const unsigned W = maskA[w] | (unsigned)maskG[w];
    unsigned v1 = maskA[lane]        | (unsigned)maskG[lane];
    unsigned v2 = maskA[lane + 32]   | (unsigned)maskG[lane + 32];
    unsigned b1 = __ballot_sync(0xffffffffu, v1 != 0);
    unsigned b2 = __ballot_sync(0xffffffffu, v2 != 0);
    const unsigned long long occ = ((unsigned long long)b2 << 32) | b1;

    int prevOut, nextOut;
    {
        unsigned long long om = (w == 0) ? 0ull : (occ & ((1ull << w) - 1ull));
        if (om) {
            int wp = 63 - __clzll(om);
            unsigned Wp = maskA[wp] | (unsigned)maskG[wp];
            prevOut = (wp << 5) + 31 - __clz(Wp);
        } else prevOut = -(1 << 30);
        unsigned long long on = (w == 63) ? 0ull : (occ >> (w + 1));
        if (on) {
            int wn = w + 1 + __ffsll((long long)on) - 1;
            unsigned Wn = maskA[wn] | (unsigned)maskG[wn];
            nextOut = (wn << 5) + __ffs(Wn) - 1;
        } else nextOut = (1 << 30);
    }

    // tmax/tmin algebra: tmax = any ? 1 : 0 (anchor => d=0 => g=1);
    // tmin = exp(coef*dmax^2) (monotone) -> only an INT max reduction needed.
    const float coef = -200.0f / ((float)(TT - 1) * (float)(TT - 1));
    int dmaxi = 0;
    float Sv = 0.0f, Sgd = 0.0f, Sd = 0.0f;
    #pragma unroll
    for (int k = 0; k < CH4; ++k) {
        int j  = base4 + k;
        int bj = j & 31;
        unsigned le = W & (0xffffffffu >> (31 - bj));
        unsigned ge = W & (0xffffffffu << bj);
        int pv = le ? ((w << 5) + 31 - __clz(le)) : prevOut;
        int nx = ge ? ((w << 5) + __ffs(ge) - 1) : nextOut;
        int d  = min(j - pv, nx - j);
        dmaxi = max(dmaxi, d);
        float fd = (float)d;
        float g = __expf(coef * fd * fd);   // ->0 when no mined elements
        float u = __logf(pp[k]);
        float v = __logf(qq[k]);
        float du = u - v;
        Sv += v;
        Sgd = fmaf(g, du, Sgd);
        Sd += du;
    }
    #pragma unroll
    for (int d = 16; d; d >>= 1) {
        dmaxi = max(dmaxi, __shfl_xor_sync(0xffffffffu, dmaxi, d));
        Sv  += __shfl_xor_sync(0xffffffffu, Sv,  d);
        Sgd += __shfl_xor_sync(0xffffffffu, Sgd, d);
        Sd  += __shfl_xor_sync(0xffffffffu, Sd,  d);
    }
    if (lane == 0) {
        rdm[wg] = dmaxi;
        rsv[wg] = Sv; rsgd[wg] = Sgd; rsd[wg] = Sd;
    }
    __syncthreads();

    // Tail: warp 0 parallel cross-warp reduce, release-atomic ticket, and
    // (last block) lane-parallel deterministic final reduce.
    if (wg == 0) {
        int   a1 = (lane < 16) ? rdm[lane]  : 0;
        float a3 = (lane < 16) ? rsv[lane]  : 0.0f;
        float a4 = (lane < 16) ? rsgd[lane] : 0.0f;
        float a5 = (lane < 16) ? rsd[lane]  : 0.0f;
        #pragma unroll
        for (int d = 8; d; d >>= 1) {
            a1 = max(a1, __shfl_xor_sync(0xffffffffu, a1, d));
            a3 += __shfl_xor_sync(0xffffffffu, a3, d);
            a4 += __shfl_xor_sync(0xffffffffu, a4, d);
            a5 += __shfl_xor_sync(0xffffffffu, a5, d);
        }
        int old = 0;
        if (lane == 0) {
            float fd  = (float)a1;
            float tmn = __expf(coef * fd * fd);
            float tmx = (occ != 0ull) ? 1.0f : 0.0f;
            float loss;
            if (tmx > tmn) {
                loss = -a3 - __fdividef(a4 - tmn * a5, tmx - tmn);
            } else {
                loss = -a3 - a4;
            }
            g_partial[b] = loss;
            // release-ordered ticket (replaces __threadfence + atomicAdd)
            asm volatile("atom.add.acq_rel.gpu.global.s32 %0, [%1], 1;"
                         : "=r"(old) : "l"(&g_count) : "memory");
        }
        old = __shfl_sync(0xffffffffu, old, 0);
        if (old == (int)gridDim.x - 1) {
            // last block: coalesced lane-parallel deterministic reduce
            float pv = __ldcg(&g_partial[lane]);   // 32 partials, one LDG
            #pragma unroll
            for (int d = 16; d; d >>= 1)
                pv += __shfl_xor_sync(0xffffffffu, pv, d);
            if (lane == 0) {
                out[0] = pv / ((float)gridDim.x * (float)TT);
                g_count = 0;     // reset for next graph replay
            }
        }
    }
}

extern "C" void kernel_launch(void* const* d_in, const int* in_sizes, int n_in,
                              void* d_out, int out_size)
{
    const float* scores      = (const float*)d_in[0];
    // d_in[1] = labels (unused by the loss)
    const int*   point_label = (const int*)d_in[2];
    const int*   seqlen      = (const int*)d_in[3];
    const int*   step_p      = (const int*)d_in[4];
    float* out = (float*)d_out;

    const int B  = in_sizes[1];   // 64
    const int nb = B / 2;         // 32 abnormal videos

    glance_fused<<<nb, NT>>>(scores, point_label, seqlen, step_p, out);
}

// round 12
// speedup vs baseline: 1.2610x; 1.2610x over previous
#include <cuda_runtime.h>
#include <math.h>

// Fixed dataset shape: B=64, NCROPS=2, T=2048, nb=32
#define TT   2048
#define NW64 64         // mask words (TT/32)
#define NT   512        // 16 warps: group0 = warps 0-7 (fwd), group1 = warps 8-15 (bwd)
#define GT   256        // threads per group
#define GCH  8          // elements per thread in group phases
#define CH4  4          // elements per thread in full-block phases
#define ALPHA_F 0.7f
#define MIN_MINING_STEP 50
#define BIGF 3.0e38f

// packed accumulator: bits [63:52] = block-arrival count, bits [51:0] = biased
// Q20 fixed-point loss sum. Integer adds are exact & order-independent ->
// deterministic output irrespective of block completion order.
__device__ unsigned long long g_acc = 0ull;

// group barrier (named): only the 256 threads of one group participate
__device__ __forceinline__ void gbar(int id) {
    asm volatile("bar.sync %0, %1;" :: "r"(id), "r"(GT) : "memory");
}

// ---- mining monoid: function (okIn,anchIn,hasIn) -> (okOut,anchOut,hasOut) ----
// fl bit0 = hasAnchor, bit1 = okPost (ok after last internal anchor)
struct MF { int fl; float aOut; float mPre; };

__device__ __forceinline__ MF mcomp(const MF L, const MF R) {
    MF C;
    const int lh = L.fl & 1, rh = R.fl & 1;
    C.aOut = rh ? R.aOut : L.aOut;
    C.mPre = lh ? L.mPre : fminf(L.mPre, R.mPre);
    int kp = rh ? (R.fl >> 1)
                : ((L.fl >> 1) & ((R.mPre >= ALPHA_F * L.aOut) ? 1 : 0));
    C.fl = (lh | rh) | ((kp & 1) << 1);
    return C;
}

// One mining direction. Returns the thread's 8-bit grown mask (bit k = idx base+k
// in direction coordinates). Exact replay of the jax scan recurrence.
__device__ __forceinline__ unsigned mine_dir(
    const float* sv, unsigned amask,
    int* sfl, float* sa, float* sm,
    int lane, int wig, int wg, int barId, int rev, int L, int base)
{
    // pass 1: serial thread aggregate (compose 8 element functions)
    MF acc;
    #pragma unroll
    for (int k = 0; k < GCH; ++k) {
        float s = sv[k];
        int   a = (amask >> k) & 1;
        MF e; e.fl = a ? 3 : 2; e.aOut = a ? s : 0.0f; e.mPre = a ? BIGF : s;
        acc = (k == 0) ? e : mcomp(acc, e);
    }

    // warp inclusive scan
    MF inc = acc;
    #pragma unroll
    for (int d = 1; d < 32; d <<= 1) {
        MF v;
        v.fl   = __shfl_up_sync(0xffffffffu, inc.fl,   d);
        v.aOut = __shfl_up_sync(0xffffffffu, inc.aOut, d);
        v.mPre = __shfl_up_sync(0xffffffffu, inc.mPre, d);
        if (lane >= d) inc = mcomp(v, inc);
    }
    if (lane == 31) { sfl[wg] = inc.fl; sa[wg] = inc.aOut; sm[wg] = inc.mPre; }
    gbar(barId);

    // cross-warp prefix: 8-lane mini scan over this group's warp aggregates
    const int wbase = wg - wig;
    MF wv;
    {
        int idxw = wbase + (lane & 7);
        wv.fl = sfl[idxw]; wv.aOut = sa[idxw]; wv.mPre = sm[idxw];
    }
    #pragma unroll
    for (int d = 1; d < 8; d <<= 1) {
        MF u;
        u.fl   = __shfl_up_sync(0xffffffffu, wv.fl,   d);
        u.aOut = __shfl_up_sync(0xffffffffu, wv.aOut, d);
        u.mPre = __shfl_up_sync(0xffffffffu, wv.mPre, d);
        if (lane >= d) wv = mcomp(u, wv);
    }
    MF wp;
    wp.fl   = __shfl_sync(0xffffffffu, wv.fl,   wig - 1);
    wp.aOut = __shfl_sync(0xffffffffu, wv.aOut, wig - 1);
    wp.mPre = __shfl_sync(0xffffffffu, wv.mPre, wig - 1);
    const int hasWp = (wig > 0);

    // thread-exclusive within warp
    MF te;
    te.fl   = __shfl_up_sync(0xffffffffu, inc.fl,   1);
    te.aOut = __shfl_up_sync(0xffffffffu, inc.aOut, 1);
    te.mPre = __shfl_up_sync(0xffffffffu, inc.mPre, 1);
    const int hasTe = (lane > 0);
    MF P; int hasP = 0;
    if (hasWp && hasTe)      { P = mcomp(wp, te); hasP = 1; }
    else if (hasWp)          { P = wp;            hasP = 1; }
    else if (hasTe)          { P = te;            hasP = 1; }

    // apply prefix to canonical init (ok=true, anch=0, has=false)
    int   has  = hasP ? (P.fl & 1) : 0;
    int   ok   = has ? ((P.fl >> 1) & 1) : 1;
    float anch = has ? P.aOut : 0.0f;

    // pass 2: serial replay emitting grown bits
    unsigned gmask = 0;
    #pragma unroll
    for (int k = 0; k < GCH; ++k) {
        float s = sv[k];
        int   a = (amask >> k) & 1;
        int cond  = (s >= ALPHA_F * anch) ? 1 : 0;
        int grown = ok & cond & has;
        if (!rev) {                       // fwd masked by seqlen
            int pos = base + k;
            grown &= (pos < L) ? 1 : 0;
        }
        gmask |= ((unsigned)grown) << k;
        ok   = a ? 1 : grown;
        anch = a ? s : anch;
        has |= a;
    }
    return gmask;
}

__global__ __launch_bounds__(NT, 1)
void glance_fused(const float* __restrict__ scores,
                  const int* __restrict__ point_label,
                  const int* __restrict__ seqlen,
                  const int* __restrict__ step_p,
                  float* __restrict__ out)
{
    const int b = blockIdx.x;
    const int t = threadIdx.x;

    __shared__ float sprob[TT];
    __shared__ unsigned maskA[NW64];   // anchors (phase 1)
    __shared__ int      maskG[NW64];   // mined growth (phase 2), OR'd atomically
    __shared__ int   sfl[16]; __shared__ float sa[16]; __shared__ float sm[16];
    __shared__ int   rdm[16];
    __shared__ float rsv[16], rsgd[16], rsd[16];

    // early scalar loads (overlap with phase 1 DRAM latency)
    const int L   = seqlen[b];
    const int stp = step_p[0];

    const int lane = t & 31, wg = t >> 5, grp = t >> 8, wig = wg & 7;
    const int gt = t & (GT - 1), barId = 1 + grp;
    const int base4 = t * CH4;

    // Phase 1: vectorized sigmoid + crop-mean. Only p and 1-p computed here
    // (3 MUFU/elem); BCE logs deferred to phase 4.
    const float4* r0 = (const float4*)(scores + (size_t)(2 * b) * TT);
    const float4* r1 = (const float4*)(scores + (size_t)(2 * b + 1) * TT);
    const int4*   pl = (const int4*)(point_label + (size_t)b * TT);
    const float4 avv = r0[t];
    const float4 cvv = r1[t];
    const int4   qvv = pl[t];
    const float aa[4] = {avv.x, avv.y, avv.z, avv.w};
    const float cc[4] = {cvv.x, cvv.y, cvv.z, cvv.w};
    const int   qq4[4] = {qvv.x, qvv.y, qvv.z, qvv.w};
    float pp[CH4], qq[CH4];
    unsigned nib = 0;
    #pragma unroll
    for (int k = 0; k < CH4; ++k) {
        float ea = __expf(-aa[k]);
        float ec = __expf(-cc[k]);
        float n1 = 2.0f + ea + ec;
        float n2 = fmaf(2.0f * ea, ec, ea + ec);
        float rc = __frcp_rn(n1 + n2);
        float p  = n1 * rc;
        sprob[base4 + k] = p;
        pp[k] = p;
        qq[k] = n2 * rc;
        nib |= ((qq4[k] > 0) ? 1u : 0u) << k;
    }
    // anchor bitmask: 8 consecutive threads' nibbles -> one 32-bit word
    {
        unsigned v = nib << ((t & 7) * 4);
        v |= __shfl_xor_sync(0xffffffffu, v, 1);
        v |= __shfl_xor_sync(0xffffffffu, v, 2);
        v |= __shfl_xor_sync(0xffffffffu, v, 4);
        if ((t & 7) == 0) maskA[t >> 3] = v;
    }
    if (t < NW64) maskG[t] = 0;
    __syncthreads();

    // Phase 2: mining — fwd (group 0) and bwd (group 1) run CONCURRENTLY.
    if (stp >= MIN_MINING_STEP) {
        const int gbase = gt * GCH;
        const float4* sp4 = (const float4*)sprob;
        float sv[GCH]; unsigned amask; int widx; unsigned plshift; int rb = 0;
        if (grp == 0) {
            float4 f0 = sp4[gbase >> 2], f1 = sp4[(gbase >> 2) + 1];
            sv[0]=f0.x; sv[1]=f0.y; sv[2]=f0.z; sv[3]=f0.w;
            sv[4]=f1.x; sv[5]=f1.y; sv[6]=f1.z; sv[7]=f1.w;
            amask = (maskA[gt >> 2] >> ((gt & 3) * 8)) & 0xffu;
            widx = gt >> 2; plshift = (gt & 3) * 8;
        } else {
            const int q = TT - 8 - gbase;      // lowest position of this byte
            float4 f0 = sp4[q >> 2], f1 = sp4[(q >> 2) + 1];
            sv[0]=f1.w; sv[1]=f1.z; sv[2]=f1.y; sv[3]=f1.x;
            sv[4]=f0.w; sv[5]=f0.z; sv[6]=f0.y; sv[7]=f0.x;
            unsigned byte = (maskA[q >> 5] >> (q & 24)) & 0xffu;
            amask = __brev(byte) >> 24;
            widx = q >> 5; plshift = q & 24; rb = 1;
        }
        unsigned gmask = mine_dir(sv, amask, sfl, sa, sm,
                                  lane, wig, wg, barId, grp, L, gbase);
        unsigned bytev = rb ? (__brev(gmask) >> 24) : gmask;
        unsigned v = bytev << plshift;
        v |= __shfl_xor_sync(0xffffffffu, v, 1);
        v |= __shfl_xor_sync(0xffffffffu, v, 2);
        if ((gt & 3) == 0 && v) atomicOr(&maskG[widx], (int)v);
    }
    __syncthreads();

    // Phase 3+4 fused: O(1) nearest-set distance from bitmask + splat + BCE.
    const int w = t >> 3;
    const unsigned W = maskA[w] | (unsigned)maskG[w];
    unsigned v1 = maskA[lane]        | (unsigned)maskG[lane];
    unsigned v2 = maskA[lane + 32]   | (unsigned)maskG[lane + 32];
    unsigned b1 = __ballot_sync(0xffffffffu, v1 != 0);
    unsigned b2 = __ballot_sync(0xffffffffu, v2 != 0);
    const unsigned long long occ = ((unsigned long long)b2 << 32) | b1;

    int prevOut, nextOut;
    {
        unsigned long long om = (w == 0) ? 0ull : (occ & ((1ull << w) - 1ull));
        if (om) {
            int wp = 63 - __clzll(om);
            unsigned Wp = maskA[wp] | (unsigned)maskG[wp];
            prevOut = (wp << 5) + 31 - __clz(Wp);
        } else prevOut = -(1 << 30);
        unsigned long long on = (w == 63) ? 0ull : (occ >> (w + 1));
        if (on) {
            int wn = w + 1 + __ffsll((long long)on) - 1;
            unsigned Wn = maskA[wn] | (unsigned)maskG[wn];
            nextOut = (wn << 5) + __ffs(Wn) - 1;
        } else nextOut = (1 << 30);
    }

    // tmax/tmin algebra: tmax = any ? 1 : 0 (anchor => d=0 => g=1);
    // tmin = exp(coef*dmax^2) (monotone) -> only an INT max reduction needed.
    const float coef = -200.0f / ((float)(TT - 1) * (float)(TT - 1));
    int dmaxi = 0;
    float Sv = 0.0f, Sgd = 0.0f, Sd = 0.0f;
    #pragma unroll
    for (int k = 0; k < CH4; ++k) {
        int j  = base4 + k;
        int bj = j & 31;
        unsigned le = W & (0xffffffffu >> (31 - bj));
        unsigned ge = W & (0xffffffffu << bj);
        int pv = le ? ((w << 5) + 31 - __clz(le)) : prevOut;
        int nx = ge ? ((w << 5) + __ffs(ge) - 1) : nextOut;
        int d  = min(j - pv, nx - j);
        dmaxi = max(dmaxi, d);
        float fd = (float)d;
        float g = __expf(coef * fd * fd);   // ->0 when no mined elements
        float u = __logf(pp[k]);
        float v = __logf(qq[k]);
        float du = u - v;
        Sv += v;
        Sgd = fmaf(g, du, Sgd);
        Sd += du;
    }
    #pragma unroll
    for (int d = 16; d; d >>= 1) {
        dmaxi = max(dmaxi, __shfl_xor_sync(0xffffffffu, dmaxi, d));
        Sv  += __shfl_xor_sync(0xffffffffu, Sv,  d);
        Sgd += __shfl_xor_sync(0xffffffffu, Sgd, d);
        Sd  += __shfl_xor_sync(0xffffffffu, Sd,  d);
    }
    if (lane == 0) {
        rdm[wg] = dmaxi;
        rsv[wg] = Sv; rsgd[wg] = Sgd; rsd[wg] = Sd;
    }
    __syncthreads();

    // Tail: warp 0 cross-warp reduce, then ONE packed 64-bit atomic that is
    // simultaneously the value accumulator, the ticket, and the final reduce.
    if (wg == 0) {
        int   a1 = (lane < 16) ? rdm[lane]  : 0;
        float a3 = (lane < 16) ? rsv[lane]  : 0.0f;
        float a4 = (lane < 16) ? rsgd[lane] : 0.0f;
        float a5 = (lane < 16) ? rsd[lane]  : 0.0f;
        #pragma unroll
        for (int d = 8; d; d >>= 1) {
            a1 = max(a1, __shfl_xor_sync(0xffffffffu, a1, d));
            a3 += __shfl_xor_sync(0xffffffffu, a3, d);
            a4 += __shfl_xor_sync(0xffffffffu, a4, d);
            a5 += __shfl_xor_sync(0xffffffffu, a5, d);
        }
        if (lane == 0) {
            float fd  = (float)a1;
            float tmn = __expf(coef * fd * fd);
            float tmx = (occ != 0ull) ? 1.0f : 0.0f;
            float loss;
            if (tmx > tmn) {
                loss = -a3 - __fdividef(a4 - tmn * a5, tmx - tmn);
            } else {
                loss = -a3 - a4;
            }
            // pack: count in [63:52], biased Q20 fixed-point sum in [51:0].
            // loss >= 0 mathematically; +2^32 bias absorbs fp rounding negatives.
            long long fix = __float2ll_rn(loss * 1048576.0f) + (1ll << 32);
            unsigned long long pkt = (1ull << 52) | (unsigned long long)fix;
            unsigned long long old = atomicAdd(&g_acc, pkt);
            if ((old >> 52) == (unsigned long long)(gridDim.x - 1)) {
                // this block completes the sum: total already in old+pkt
                unsigned long long tot = (old + pkt) & ((1ull << 52) - 1ull);
                long long s = (long long)tot
                            - ((long long)gridDim.x << 32);   // remove biases
                float lossSum = (float)s * (1.0f / 1048576.0f);
                out[0] = lossSum / ((float)gridDim.x * (float)TT);
                g_acc = 0ull;          // reset for next graph replay
            }
        }
    }
}

extern "C" void kernel_launch(void* const* d_in, const int* in_sizes, int n_in,
                              void* d_out, int out_size)
{
    const float* scores      = (const float*)d_in[0];
    // d_in[1] = labels (unused by the loss)
    const int*   point_label = (const int*)d_in[2];
    const int*   seqlen      = (const int*)d_in[3];
    const int*   step_p      = (const int*)d_in[4];
    float* out = (float*)d_out;

    const int B  = in_sizes[1];   // 64
    const int nb = B / 2;         // 32 abnormal videos

    glance_fused<<<nb, NT>>>(scores, point_label, seqlen, step_p, out);
}

// round 13
// speedup vs baseline: 1.2657x; 1.0037x over previous
#include <cuda_runtime.h>
#include <math.h>

// Fixed dataset shape: B=64, NCROPS=2, T=2048, nb=32
#define TT   2048
#define NW64 64         // mask words (TT/32)
#define NT   1024       // 32 warps: group0 = warps 0-15 (fwd), group1 = warps 16-31 (bwd)
#define GT   512        // threads per group
#define GCH  4          // elements per thread in group (mining) phases
#define CH2  2          // elements per thread in full-block phases
#define ALPHA_F 0.7f
#define MIN_MINING_STEP 50
#define BIGF 3.0e38f

// packed accumulator: bits [63:52] = block-arrival count, bits [51:0] = biased
// Q20 fixed-point loss sum. Integer adds are exact & order-independent ->
// deterministic output irrespective of block completion order.
__device__ unsigned long long g_acc = 0ull;

// group barrier (named): only the 512 threads of one group participate
__device__ __forceinline__ void gbar(int id) {
    asm volatile("bar.sync %0, %1;" :: "r"(id), "r"(GT) : "memory");
}

// ---- mining monoid: function (okIn,anchIn,hasIn) -> (okOut,anchOut,hasOut) ----
// fl bit0 = hasAnchor, bit1 = okPost (ok after last internal anchor)
struct MF { int fl; float aOut; float mPre; };

__device__ __forceinline__ MF mcomp(const MF L, const MF R) {
    MF C;
    const int lh = L.fl & 1, rh = R.fl & 1;
    C.aOut = rh ? R.aOut : L.aOut;
    C.mPre = lh ? L.mPre : fminf(L.mPre, R.mPre);
    int kp = rh ? (R.fl >> 1)
                : ((L.fl >> 1) & ((R.mPre >= ALPHA_F * L.aOut) ? 1 : 0));
    C.fl = (lh | rh) | ((kp & 1) << 1);
    return C;
}

// One mining direction. Returns the thread's 4-bit grown mask (bit k = idx base+k
// in direction coordinates). Exact replay of the jax scan recurrence.
__device__ __forceinline__ unsigned mine_dir(
    const float* sv, unsigned amask,
    int* sfl, float* sa, float* sm,
    int lane, int wig, int wg, int barId, int rev, int L, int base)
{
    // pass 1: serial thread aggregate (compose 4 element functions)
    MF acc;
    #pragma unroll
    for (int k = 0; k < GCH; ++k) {
        float s = sv[k];
        int   a = (amask >> k) & 1;
        MF e; e.fl = a ? 3 : 2; e.aOut = a ? s : 0.0f; e.mPre = a ? BIGF : s;
        acc = (k == 0) ? e : mcomp(acc, e);
    }

    // warp inclusive scan
    MF inc = acc;
    #pragma unroll
    for (int d = 1; d < 32; d <<= 1) {
        MF v;
        v.fl   = __shfl_up_sync(0xffffffffu, inc.fl,   d);
        v.aOut = __shfl_up_sync(0xffffffffu, inc.aOut, d);
        v.mPre = __shfl_up_sync(0xffffffffu, inc.mPre, d);
        if (lane >= d) inc = mcomp(v, inc);
    }
    if (lane == 31) { sfl[wg] = inc.fl; sa[wg] = inc.aOut; sm[wg] = inc.mPre; }
    gbar(barId);

    // cross-warp prefix: 16-lane mini scan over this group's warp aggregates
    const int wbase = wg - wig;
    MF wv;
    {
        int idxw = wbase + (lane & 15);
        wv.fl = sfl[idxw]; wv.aOut = sa[idxw]; wv.mPre = sm[idxw];
    }
    #pragma unroll
    for (int d = 1; d < 16; d <<= 1) {
        MF u;
        u.fl   = __shfl_up_sync(0xffffffffu, wv.fl,   d);
        u.aOut = __shfl_up_sync(0xffffffffu, wv.aOut, d);
        u.mPre = __shfl_up_sync(0xffffffffu, wv.mPre, d);
        if (lane >= d) wv = mcomp(u, wv);
    }
    MF wp;
    wp.fl   = __shfl_sync(0xffffffffu, wv.fl,   wig - 1);
    wp.aOut = __shfl_sync(0xffffffffu, wv.aOut, wig - 1);
    wp.mPre = __shfl_sync(0xffffffffu, wv.mPre, wig - 1);
    const int hasWp = (wig > 0);

    // thread-exclusive within warp
    MF te;
    te.fl   = __shfl_up_sync(0xffffffffu, inc.fl,   1);
    te.aOut = __shfl_up_sync(0xffffffffu, inc.aOut, 1);
    te.mPre = __shfl_up_sync(0xffffffffu, inc.mPre, 1);
    const int hasTe = (lane > 0);
    MF P; int hasP = 0;
    if (hasWp && hasTe)      { P = mcomp(wp, te); hasP = 1; }
    else if (hasWp)          { P = wp;            hasP = 1; }
    else if (hasTe)          { P = te;            hasP = 1; }

    // apply prefix to canonical init (ok=true, anch=0, has=false)
    int   has  = hasP ? (P.fl & 1) : 0;
    int   ok   = has ? ((P.fl >> 1) & 1) : 1;
    float anch = has ? P.aOut : 0.0f;

    // pass 2: serial replay emitting grown bits
    unsigned gmask = 0;
    #pragma unroll
    for (int k = 0; k < GCH; ++k) {
        float s = sv[k];
        int   a = (amask >> k) & 1;
        int cond  = (s >= ALPHA_F * anch) ? 1 : 0;
        int grown = ok & cond & has;
        if (!rev) {                       // fwd masked by seqlen
            int pos = base + k;
            grown &= (pos < L) ? 1 : 0;
        }
        gmask |= ((unsigned)grown) << k;
        ok   = a ? 1 : grown;
        anch = a ? s : anch;
        has |= a;
    }
    return gmask;
}

__global__ __launch_bounds__(NT, 1)
void glance_fused(const float* __restrict__ scores,
                  const int* __restrict__ point_label,
                  const int* __restrict__ seqlen,
                  const int* __restrict__ step_p,
                  float* __restrict__ out)
{
    const int b = blockIdx.x;
    const int t = threadIdx.x;

    __shared__ float sprob[TT];
    __shared__ unsigned maskA[NW64];   // anchors (phase 1)
    __shared__ int      maskG[NW64];   // mined growth (phase 2), OR'd atomically
    __shared__ int   sfl[32]; __shared__ float sa[32]; __shared__ float sm[32];
    __shared__ int   rdm[32];
    __shared__ float rsv[32], rsgd[32], rsd[32];

    // early scalar loads (overlap with phase 1 DRAM latency)
    const int L   = seqlen[b];
    const int stp = step_p[0];

    const int lane = t & 31, wg = t >> 5, grp = t >> 9, wig = wg & 15;
    const int gt = t & (GT - 1), barId = 1 + grp;
    const int base2 = t * CH2;

    // Phase 1: vectorized sigmoid + crop-mean (2 elems/thread).
    //   ea=e^-a, ec=e^-c; num1=2+ea+ec; num2=2*ea*ec+ea+ec; den=num1+num2
    //   p = num1/den ; 1-p = num2/den   (BCE logs deferred to phase 4)
    const float2* r0 = (const float2*)(scores + (size_t)(2 * b) * TT);
    const float2* r1 = (const float2*)(scores + (size_t)(2 * b + 1) * TT);
    const int2*   pl = (const int2*)(point_label + (size_t)b * TT);
    const float2 avv = r0[t];
    const float2 cvv = r1[t];
    const int2   qvv = pl[t];
    const float aa[2] = {avv.x, avv.y};
    const float cc[2] = {cvv.x, cvv.y};
    const int   qp[2] = {qvv.x, qvv.y};
    float pp[CH2], qq[CH2];
    unsigned nib = 0;
    #pragma unroll
    for (int k = 0; k < CH2; ++k) {
        float ea = __expf(-aa[k]);
        float ec = __expf(-cc[k]);
        float n1 = 2.0f + ea + ec;
        float n2 = fmaf(2.0f * ea, ec, ea + ec);
        float rc = __frcp_rn(n1 + n2);
        float p  = n1 * rc;
        sprob[base2 + k] = p;
        pp[k] = p;
        qq[k] = n2 * rc;
        nib |= ((qp[k] > 0) ? 1u : 0u) << k;
    }
    // anchor bitmask: 16 consecutive threads' 2-bit pieces -> one 32-bit word
    {
        unsigned v = nib << ((t & 15) * 2);
        v |= __shfl_xor_sync(0xffffffffu, v, 1);
        v |= __shfl_xor_sync(0xffffffffu, v, 2);
        v |= __shfl_xor_sync(0xffffffffu, v, 4);
        v |= __shfl_xor_sync(0xffffffffu, v, 8);
        if ((t & 15) == 0) maskA[t >> 4] = v;
    }
    if (t < NW64) maskG[t] = 0;
    __syncthreads();

    // Phase 2: mining — fwd (group 0) and bwd (group 1) run CONCURRENTLY.
    if (stp >= MIN_MINING_STEP) {
        const int gbase = gt * GCH;
        const float4* sp4 = (const float4*)sprob;
        float sv[GCH]; unsigned amask; int widx; unsigned plshift; int rb = 0;
        if (grp == 0) {
            float4 f = sp4[gt];                 // one aligned float4 = 4 elems
            sv[0]=f.x; sv[1]=f.y; sv[2]=f.z; sv[3]=f.w;
            amask = (maskA[gt >> 3] >> ((gt & 7) * 4)) & 0xfu;
            widx = gt >> 3; plshift = (gt & 7) * 4;
        } else {
            const int q = TT - 4 - gbase;       // lowest position of this nibble
            float4 f = sp4[q >> 2];
            sv[0]=f.w; sv[1]=f.z; sv[2]=f.y; sv[3]=f.x;
            unsigned nibv = (maskA[q >> 5] >> (q & 28)) & 0xfu;
            amask = __brev(nibv) >> 28;
            widx = q >> 5; plshift = q & 28; rb = 1;
        }
        unsigned gmask = mine_dir(sv, amask, sfl, sa, sm,
                                  lane, wig, wg, barId, grp, L, gbase);
        unsigned nib2 = rb ? (__brev(gmask) >> 28) : gmask;
        unsigned v = nib2 << plshift;
        v |= __shfl_xor_sync(0xffffffffu, v, 1);
        v |= __shfl_xor_sync(0xffffffffu, v, 2);
        v |= __shfl_xor_sync(0xffffffffu, v, 4);
        if ((gt & 7) == 0 && v) atomicOr(&maskG[widx], (int)v);
    }
    __syncthreads();

    // Phase 3+4 fused: O(1) nearest-set distance from bitmask + splat + BCE.
    // occupancy mask rebuilt per-warp (2 LDS + 2 ballots, no barrier).
    const int w = t >> 4;      // word holding both of this thread's positions
    const unsigned W = maskA[w] | (unsigned)maskG[w];
    unsigned v1 = maskA[lane]        | (unsigned)maskG[lane];
    unsigned v2 = maskA[lane + 32]   | (unsigned)maskG[lane + 32];
    unsigned b1 = __ballot_sync(0xffffffffu, v1 != 0);
    unsigned b2 = __ballot_sync(0xffffffffu, v2 != 0);
    const unsigned long long occ = ((unsigned long long)b2 << 32) | b1;

    int prevOut, nextOut;
    {
        unsigned long long om = (w == 0) ? 0ull : (occ & ((1ull << w) - 1ull));
        if (om) {
            int wp = 63 - __clzll(om);
            unsigned Wp = maskA[wp] | (unsigned)maskG[wp];
            prevOut = (wp << 5) + 31 - __clz(Wp);
        } else prevOut = -(1 << 30);
        unsigned long long on = (w == 63) ? 0ull : (occ >> (w + 1));
        if (on) {
            int wn = w + 1 + __ffsll((long long)on) - 1;
            unsigned Wn = maskA[wn] | (unsigned)maskG[wn];
            nextOut = (wn << 5) + __ffs(Wn) - 1;
        } else nextOut = (1 << 30);
    }

    // tmax/tmin algebra: tmax = any ? 1 : 0 (anchor => d=0 => g=1);
    // tmin = exp(coef*dmax^2) (monotone) -> only an INT max reduction needed.
    const float coef = -200.0f / ((float)(TT - 1) * (float)(TT - 1));
    int dmaxi = 0;
    float Sv = 0.0f, Sgd = 0.0f, Sd = 0.0f;
    #pragma unroll
    for (int k = 0; k < CH2; ++k) {
        int j  = base2 + k;
        int bj = j & 31;
        unsigned le = W & (0xffffffffu >> (31 - bj));
        unsigned ge = W & (0xffffffffu << bj);
        int pv = le ? ((w << 5) + 31 - __clz(le)) : prevOut;
        int nx = ge ? ((w << 5) + __ffs(ge) - 1) : nextOut;
        int d  = min(j - pv, nx - j);
        dmaxi = max(dmaxi, d);
        float fd = (float)d;
        float g = __expf(coef * fd * fd);   // ->0 when no mined elements
        float u = __logf(pp[k]);
        float v = __logf(qq[k]);
        float du = u - v;
        Sv += v;
        Sgd = fmaf(g, du, Sgd);
        Sd += du;
    }
    #pragma unroll
    for (int d = 16; d; d >>= 1) {
        dmaxi = max(dmaxi, __shfl_xor_sync(0xffffffffu, dmaxi, d));
        Sv  += __shfl_xor_sync(0xffffffffu, Sv,  d);
        Sgd += __shfl_xor_sync(0xffffffffu, Sgd, d);
        Sd  += __shfl_xor_sync(0xffffffffu, Sd,  d);
    }
    if (lane == 0) {
        rdm[wg] = dmaxi;
        rsv[wg] = Sv; rsgd[wg] = Sgd; rsd[wg] = Sd;
    }
    __syncthreads();

    // Tail: warp 0 cross-warp reduce (32 lanes, one per warp), then ONE packed
    // 64-bit atomic = value accumulator + ticket + final reduce simultaneously.
    if (wg == 0) {
        int   a1 = rdm[lane];
        float a3 = rsv[lane];
        float a4 = rsgd[lane];
        float a5 = rsd[lane];
        #pragma unroll
        for (int d = 16; d; d >>= 1) {
            a1 = max(a1, __shfl_xor_sync(0xffffffffu, a1, d));
            a3 += __shfl_xor_sync(0xffffffffu, a3, d);
            a4 += __shfl_xor_sync(0xffffffffu, a4, d);
            a5 += __shfl_xor_sync(0xffffffffu, a5, d);
        }
        if (lane == 0) {
            float fd  = (float)a1;
            float tmn = __expf(coef * fd * fd);
            float tmx = (occ != 0ull) ? 1.0f : 0.0f;
            float loss;
            if (tmx > tmn) {
                loss = -a3 - __fdividef(a4 - tmn * a5, tmx - tmn);
            } else {
                loss = -a3 - a4;
            }
            // pack: count in [63:52], biased Q20 fixed-point sum in [51:0].
            // loss >= 0 mathematically; +2^32 bias absorbs fp rounding negatives.
            long long fix = __float2ll_rn(loss * 1048576.0f) + (1ll << 32);
            unsigned long long pkt = (1ull << 52) | (unsigned long long)fix;
            unsigned long long old = atomicAdd(&g_acc, pkt);
            if ((old >> 52) == (unsigned long long)(gridDim.x - 1)) {
                // this block completes the sum: total already in old+pkt
                unsigned long long tot = (old + pkt) & ((1ull << 52) - 1ull);
                long long s = (long long)tot
                            - ((long long)gridDim.x << 32);   // remove biases
                float lossSum = (float)s * (1.0f / 1048576.0f);
                out[0] = lossSum / ((float)gridDim.x * (float)TT);
                g_acc = 0ull;          // reset for next graph replay
            }
        }
    }
}

extern "C" void kernel_launch(void* const* d_in, const int* in_sizes, int n_in,
                              void* d_out, int out_size)
{
    const float* scores      = (const float*)d_in[0];
    // d_in[1] = labels (unused by the loss)
    const int*   point_label = (const int*)d_in[2];
    const int*   seqlen      = (const int*)d_in[3];
    const int*   step_p      = (const int*)d_in[4];
    float* out = (float*)d_out;

    const int B  = in_sizes[1];   // 64
    const int nb = B / 2;         // 32 abnormal videos

    glance_fused<<<nb, NT>>>(scores, point_label, seqlen, step_p, out);
}